// round 10
// baseline (speedup 1.0000x reference)
#include <cuda_runtime.h>
#include <math.h>
#include <stdint.h>

#define KNUM 1024
#define DNUM 64
#define NNUM 32768
#define TB   128            // threads per block = tokens per block
#define NBLK (NNUM / TB)    // 256
#define CH   128            // codes per smem chunk (64 pairs, 32 KB)
#define NPAIR (CH / 2)      // 64 pairs per chunk
#define NCHUNK (KNUM / CH)  // 8
#define HWB  6
#define DUAL_STEPS 10

// ---- smem layout (dynamic) ----
#define SPK0  0             // chunk buffer 0: 64*64*8 = 32768 B
#define SPK1  32768         // chunk buffer 1
#define SCCP  65536         // 512 packed cc pairs = 4096 B
#define SRED  69632         // 128 f32
#define SM_TOTAL 70144

// ---- device scratch ----
__device__ float g_cc[KNUM];
__device__ unsigned long long g_ccpk[KNUM / 2];       // packed {cc[2p], cc[2p+1]}
__device__ unsigned long long g_pk[KNUM / 2 * DNUM];  // packed codebook {c[2p][d], c[2p+1][d]}
__device__ int   g_hist[KNUM];      // zero at load; finalize re-zeroes each replay
__device__ float g_msep[NBLK];

// ---- packed f32x2 helpers (each lane = scalar IEEE-rn op) ----
__device__ __forceinline__ void fma2(unsigned long long& acc,
                                     unsigned long long a, unsigned long long b) {
    asm("fma.rn.f32x2 %0, %1, %2, %0;" : "+l"(acc) : "l"(a), "l"(b));
}
__device__ __forceinline__ unsigned long long add2(unsigned long long a, unsigned long long b) {
    unsigned long long r;
    asm("add.rn.f32x2 %0, %1, %2;" : "=l"(r) : "l"(a), "l"(b));
    return r;
}
__device__ __forceinline__ unsigned long long mul2(unsigned long long a, unsigned long long b) {
    unsigned long long r;
    asm("mul.rn.f32x2 %0, %1, %2;" : "=l"(r) : "l"(a), "l"(b));
    return r;
}
__device__ __forceinline__ unsigned long long dup2(float v) {
    unsigned long long r;
    asm("mov.b64 %0, {%1, %1};" : "=l"(r) : "f"(v));
    return r;
}
__device__ __forceinline__ void unpk(float& lo, float& hi, unsigned long long v) {
    asm("mov.b64 {%0, %1}, %2;" : "=f"(lo), "=f"(hi) : "l"(v));
}

// ---- cp.async ----
__device__ __forceinline__ void cp_async16(uint32_t dst, const void* src) {
    asm volatile("cp.async.ca.shared.global [%0], [%1], 16;" :: "r"(dst), "l"(src));
}
__device__ __forceinline__ void cp_commit() {
    asm volatile("cp.async.commit_group;" ::: "memory");
}
__device__ __forceinline__ void cp_wait1() {
    asm volatile("cp.async.wait_group 1;" ::: "memory");
}

// ============================================================
// Kernel 0a: cc via the bit-exact sequential fmaf chain
// ============================================================
__global__ __launch_bounds__(128) void prep_cc(const float* __restrict__ cb) {
    int j = blockIdx.x * 128 + threadIdx.x;
    const float* r = cb + (size_t)j * DNUM;
    float s = 0.f;
    #pragma unroll
    for (int d = 0; d < DNUM; ++d) s = fmaf(r[d], r[d], s);
    g_cc[j] = s;
}

// ============================================================
// Kernel 0b: pack codebook + cc pairwise over codes
// ============================================================
__global__ __launch_bounds__(128) void prep_pack(const float* __restrict__ cb) {
    int p = blockIdx.x * 128 + threadIdx.x;   // pair id, grid 4 => 512 pairs
    const float* r0 = cb + (size_t)(2 * p) * DNUM;
    const float* r1 = r0 + DNUM;
    unsigned long long* dst = g_pk + (size_t)p * DNUM;
    #pragma unroll
    for (int d = 0; d < DNUM; ++d) {
        dst[d] = (unsigned long long)__float_as_uint(r0[d]) |
                 ((unsigned long long)__float_as_uint(r1[d]) << 32);
    }
    g_ccpk[p] = (unsigned long long)__float_as_uint(g_cc[2 * p]) |
                ((unsigned long long)__float_as_uint(g_cc[2 * p + 1]) << 32);
}

// ============================================================
// Kernel 1: per-token argmin, reference f32 numerics via f32x2.
// Every packed op is the per-lane rn-rounded op in the proven
// scalar order:  t=(a0+a1)+(a2+a3); u=fl(xxr+cc); dk=fl(u-2t).
// ============================================================
__global__ __launch_bounds__(TB, 3) void assign_kernel(const float* __restrict__ x,
                                                       const float* __restrict__ cb,
                                                       float* __restrict__ out) {
    extern __shared__ char smem[];
    unsigned long long* ccp = (unsigned long long*)(smem + SCCP);
    float* sred = (float*)(smem + SRED);
    const uint32_t smem_b = (uint32_t)__cvta_generic_to_shared(smem);

    const int tid = threadIdx.x;
    const int n   = blockIdx.x * TB + tid;
    const int b   = n >> 10;
    const int hw  = n & 1023;
    const float* xp = x + (size_t)b * (DNUM * 1024) + hw;

    { // cc pairs into smem
        const uint4* s4 = (const uint4*)g_ccpk;
        uint4*       d4 = (uint4*)ccp;
        #pragma unroll
        for (int i = tid; i < KNUM / 4; i += TB) d4[i] = s4[i];
    }

    // prologue prefetch: chunks 0,1 (each thread copies its 256 B)
    {
        const char* src0 = (const char*)g_pk + tid * 256;
        #pragma unroll
        for (int i = 0; i < 16; ++i)
            cp_async16(smem_b + SPK0 + tid * 256 + i * 16, src0 + i * 16);
        cp_commit();
        const char* src1 = (const char*)g_pk + 32768 + tid * 256;
        #pragma unroll
        for (int i = 0; i < 16; ++i)
            cp_async16(smem_b + SPK1 + tid * 256 + i * 16, src1 + i * 16);
        cp_commit();
    }

    // ---- load x, bit-exact xxr tree, duplicated f32x2 x regs
    unsigned long long xd[DNUM];
    float xxr;
    {
        float xf[DNUM];
        #pragma unroll
        for (int c = 0; c < DNUM; ++c) xf[c] = xp[(size_t)c * 1024];

        float p[32];
        #pragma unroll
        for (int l = 0; l < 32; ++l)
            p[l] = __fadd_rn(__fmul_rn(xf[l], xf[l]), __fmul_rn(xf[l + 32], xf[l + 32]));
        #pragma unroll
        for (int off = 16; off > 0; off >>= 1)
            #pragma unroll
            for (int l = 0; l < 16; ++l)
                if (l < off) p[l] = __fadd_rn(p[l], p[l + off]);
        xxr = p[0];

        #pragma unroll
        for (int d = 0; d < DNUM; ++d) xd[d] = dup2(xf[d]);
    }
    const unsigned long long xxd  = dup2(xxr);
    const unsigned long long neg2 = dup2(-2.0f);

    float best = INFINITY;
    int   bidx = 0;

    for (int c = 0; c < NCHUNK; ++c) {
        const int bufo = (c & 1) ? SPK1 : SPK0;
        cp_wait1();            // chunk c's group complete (≤1 group pending)
        __syncthreads();

        const unsigned long long* spk = (const unsigned long long*)(smem + bufo);
        for (int pp = 0; pp < NPAIR; ++pp) {
            const ulonglong2* cp2 = (const ulonglong2*)(spk + pp * DNUM);
            unsigned long long a0 = 0ull, a1 = 0ull, a2 = 0ull, a3 = 0ull;
            #pragma unroll
            for (int c4 = 0; c4 < 16; ++c4) {
                ulonglong2 v01 = cp2[2 * c4];
                ulonglong2 v23 = cp2[2 * c4 + 1];
                fma2(a0, xd[4 * c4 + 0], v01.x);
                fma2(a1, xd[4 * c4 + 1], v01.y);
                fma2(a2, xd[4 * c4 + 2], v23.x);
                fma2(a3, xd[4 * c4 + 3], v23.y);
            }
            const int pj = c * NPAIR + pp;
            // packed reference assembly (per-lane == proven scalar sequence)
            unsigned long long t2  = add2(add2(a0, a1), add2(a2, a3));
            unsigned long long u2  = add2(xxd, ccp[pj]);
            unsigned long long dk2 = add2(u2, mul2(neg2, t2));
            float dkl, dkh;
            unpk(dkl, dkh, dk2);
            const int j0 = 2 * pj;
            if (dkl < best) { best = dkl; bidx = j0; }      // strict <, ascending
            if (dkh < best) { best = dkh; bidx = j0 + 1; }
        }

        __syncthreads();       // all warps done reading buf before overwrite
        if (c + 2 < NCHUNK) {
            const char* src = (const char*)g_pk + (size_t)(c + 2) * 32768 + tid * 256;
            #pragma unroll
            for (int i = 0; i < 16; ++i)
                cp_async16(smem_b + bufo + tid * 256 + i * 16, src + i * 16);
            cp_commit();
        } else {
            cp_commit();       // keep group accounting uniform
        }
    }

    atomicAdd(&g_hist[bidx], 1);

    // quantized output (= chosen codeword) + MSE; x lanes from xd
    const float* cw = cb + (size_t)bidx * DNUM;
    float*       op = out + (size_t)b * (DNUM * 1024) + hw;
    float mse = 0.f;
    #pragma unroll
    for (int cdim = 0; cdim < DNUM; ++cdim) {
        float cv = cw[cdim];
        op[(size_t)cdim * 1024] = cv;
        float xl, xh;
        unpk(xl, xh, xd[cdim]);
        float dd = cv - xl;
        mse = fmaf(dd, dd, mse);
    }

    __syncthreads();
    sred[tid] = mse;
    __syncthreads();
    for (int s = TB / 2; s > 0; s >>= 1) {
        if (tid < s) sred[tid] += sred[tid + s];
        __syncthreads();
    }
    if (tid == 0) g_msep[blockIdx.x] = sred[0];
}

// ============================================================
// Kernel 2: perplexity, entropic-OT dual ascent, loss.
// __expf only inside the gradient loop (phi enters loss linearly).
// ============================================================
__device__ __forceinline__ float bred(float v, float* red, int t) {
    __syncthreads();
    red[t] = v;
    __syncthreads();
    for (int s = 512; s > 0; s >>= 1) {
        if (t < s) red[t] += red[t + s];
        __syncthreads();
    }
    float r = red[0];
    __syncthreads();
    return r;
}

__global__ __launch_bounds__(1024) void finalize_kernel(float* __restrict__ out) {
    __shared__ float s_src[KNUM], s_tgt[KNUM], s_phi[KNUM], s_lse[KNUM];
    __shared__ float red[1024];
    const int t = threadIdx.x;

    const int hraw = g_hist[t];
    g_hist[t] = 0;
    const float hist = (float)hraw * (1.0f / 32768.0f);

    float ent  = hist * logf(hist + 1e-10f);
    float esum = bred(ent, red, t);
    float perp = expf(-esum);

    float sr  = fmaxf(hist, 1e-12f);
    float ss1 = bred(sr, red, t);
    sr = sr / ss1;
    sr = fmaxf(sr, 1e-12f);
    float ss2 = bred(sr, red, t);
    sr = sr / ss2;
    s_src[t] = sr;

    float z  = ((float)t - 511.5f) / (1024.0f / 6.0f);
    float tg = expf(-0.5f * z * z);
    float ts1 = bred(tg, red, t);
    tg = tg / fmaxf(ts1, 1e-12f);
    tg = fmaxf(tg, 1e-12f);
    float ts2 = bred(tg, red, t);
    tg = tg / ts2;
    s_tgt[t] = tg;
    const float ltg_t = logf(fmaxf(tg, 1e-12f));
    s_phi[t] = 0.f;
    __syncthreads();

    const int lo = (t - HWB < 0) ? 0 : t - HWB;
    const int hi = (t + HWB > KNUM - 1) ? KNUM - 1 : t + HWB;

    float phi_t = 0.f;
    for (int step = 0; step < DUAL_STEPS; ++step) {
        s_lse[t] = __fadd_rn(ltg_t, __fmul_rn(phi_t, 20.0f));
        __syncthreads();
        float cs = 0.f;
        for (int i = lo; i <= hi; ++i) {
            float c = fabsf((float)(i - t));
            float a = __fadd_rn(ltg_t, __fmul_rn(__fadd_rn(-c, phi_t), 20.0f));
            cs = fmaf(s_src[i], __expf(a - s_lse[i]), cs);
        }
        __syncthreads();
        phi_t = phi_t + 0.5f * (s_tgt[t] - cs);
        s_phi[t] = phi_t;
        __syncthreads();
    }

    float lse_t = __fadd_rn(ltg_t, __fmul_rn(phi_t, 20.0f));
    float obj = sr * (-0.05f * lse_t) + s_tgt[t] * phi_t;
    float ot  = bred(obj, red, t);

    float mp   = (t < NBLK) ? g_msep[t] : 0.f;
    float msum = bred(mp, red, t);
    float mse  = msum * (1.0f / 2097152.0f);

    if (t == 0) {
        float loss = mse + 0.25f * mse + 1.0f * ot;
        out[2097152] = loss;
        out[2097153] = perp;
    }
}

// ============================================================
extern "C" void kernel_launch(void* const* d_in, const int* in_sizes, int n_in,
                              void* d_out, int out_size) {
    const float* x  = (const float*)d_in[0];
    const float* cb = (const float*)d_in[1];
    float* out = (float*)d_out;
    (void)in_sizes; (void)n_in; (void)out_size;

    cudaFuncSetAttribute(assign_kernel,
                         cudaFuncAttributeMaxDynamicSharedMemorySize, SM_TOTAL);

    prep_cc<<<8, 128>>>(cb);
    prep_pack<<<4, 128>>>(cb);
    assign_kernel<<<NBLK, TB, SM_TOTAL>>>(x, cb, out);
    finalize_kernel<<<1, 1024>>>(out);
}

// round 11
// speedup vs baseline: 1.0003x; 1.0003x over previous
#include <cuda_runtime.h>
#include <math.h>
#include <stdint.h>

#define KNUM 1024
#define DNUM 64
#define NNUM 32768
#define TB   128            // threads per block = tokens per block
#define NBLK (NNUM / TB)    // 256
#define CH   128            // codes per smem chunk (64 pairs, 32 KB)
#define NPAIR (CH / 2)      // 64 pairs per chunk
#define NCHUNK (KNUM / CH)  // 8
#define HWB  6
#define DUAL_STEPS 10

// ---- smem layout (dynamic) ----
#define SPK0  0             // chunk buffer 0: 64*64*8 = 32768 B
#define SPK1  32768         // chunk buffer 1
#define SCCP  65536         // 512 packed cc pairs = 4096 B
#define SRED  69632         // 128 f32
#define SM_TOTAL 70144

// ---- device scratch ----
__device__ float g_cc[KNUM];
__device__ unsigned long long g_ccpk[KNUM / 2];       // packed {cc[2p], cc[2p+1]}
__device__ unsigned long long g_pk[KNUM / 2 * DNUM];  // packed codebook {c[2p][d], c[2p+1][d]}
__device__ int   g_hist[KNUM];      // zero at load; finalize re-zeroes each replay
__device__ float g_msep[NBLK];

// ---- packed f32x2 helpers (each lane = scalar IEEE-rn op) ----
__device__ __forceinline__ void fma2(unsigned long long& acc,
                                     unsigned long long a, unsigned long long b) {
    asm("fma.rn.f32x2 %0, %1, %2, %0;" : "+l"(acc) : "l"(a), "l"(b));
}
__device__ __forceinline__ unsigned long long add2(unsigned long long a, unsigned long long b) {
    unsigned long long r;
    asm("add.rn.f32x2 %0, %1, %2;" : "=l"(r) : "l"(a), "l"(b));
    return r;
}
__device__ __forceinline__ unsigned long long mul2(unsigned long long a, unsigned long long b) {
    unsigned long long r;
    asm("mul.rn.f32x2 %0, %1, %2;" : "=l"(r) : "l"(a), "l"(b));
    return r;
}
__device__ __forceinline__ unsigned long long dup2(float v) {
    unsigned long long r;
    asm("mov.b64 %0, {%1, %1};" : "=l"(r) : "f"(v));
    return r;
}
__device__ __forceinline__ void unpk(float& lo, float& hi, unsigned long long v) {
    asm("mov.b64 {%0, %1}, %2;" : "=f"(lo), "=f"(hi) : "l"(v));
}

// ---- cp.async ----
__device__ __forceinline__ void cp_async16(uint32_t dst, const void* src) {
    asm volatile("cp.async.ca.shared.global [%0], [%1], 16;" :: "r"(dst), "l"(src));
}
__device__ __forceinline__ void cp_commit() {
    asm volatile("cp.async.commit_group;" ::: "memory");
}
__device__ __forceinline__ void cp_wait1() {
    asm volatile("cp.async.wait_group 1;" ::: "memory");
}

// ============================================================
// Kernel 0a: cc via the bit-exact sequential fmaf chain
// ============================================================
__global__ __launch_bounds__(128) void prep_cc(const float* __restrict__ cb) {
    int j = blockIdx.x * 128 + threadIdx.x;
    const float* r = cb + (size_t)j * DNUM;
    float s = 0.f;
    #pragma unroll
    for (int d = 0; d < DNUM; ++d) s = fmaf(r[d], r[d], s);
    g_cc[j] = s;
}

// ============================================================
// Kernel 0b: pack codebook + cc pairwise over codes
// ============================================================
__global__ __launch_bounds__(128) void prep_pack(const float* __restrict__ cb) {
    int p = blockIdx.x * 128 + threadIdx.x;   // pair id, grid 4 => 512 pairs
    const float* r0 = cb + (size_t)(2 * p) * DNUM;
    const float* r1 = r0 + DNUM;
    unsigned long long* dst = g_pk + (size_t)p * DNUM;
    #pragma unroll
    for (int d = 0; d < DNUM; ++d) {
        dst[d] = (unsigned long long)__float_as_uint(r0[d]) |
                 ((unsigned long long)__float_as_uint(r1[d]) << 32);
    }
    g_ccpk[p] = (unsigned long long)__float_as_uint(g_cc[2 * p]) |
                ((unsigned long long)__float_as_uint(g_cc[2 * p + 1]) << 32);
}

// ============================================================
// Kernel 1: per-token argmin, reference f32 numerics via f32x2.
// Every packed op is the per-lane rn-rounded op in the proven
// scalar order:  t=(a0+a1)+(a2+a3); u=fl(xxr+cc); dk=fl(u-2t).
// occupancy 2 (NOT 3): xd[64] must stay register-resident.
// ============================================================
__global__ __launch_bounds__(TB, 2) void assign_kernel(const float* __restrict__ x,
                                                       const float* __restrict__ cb,
                                                       float* __restrict__ out) {
    extern __shared__ char smem[];
    unsigned long long* ccp = (unsigned long long*)(smem + SCCP);
    float* sred = (float*)(smem + SRED);
    const uint32_t smem_b = (uint32_t)__cvta_generic_to_shared(smem);

    const int tid = threadIdx.x;
    const int n   = blockIdx.x * TB + tid;
    const int b   = n >> 10;
    const int hw  = n & 1023;
    const float* xp = x + (size_t)b * (DNUM * 1024) + hw;

    { // cc pairs into smem
        const uint4* s4 = (const uint4*)g_ccpk;
        uint4*       d4 = (uint4*)ccp;
        #pragma unroll
        for (int i = tid; i < KNUM / 4; i += TB) d4[i] = s4[i];
    }

    // prologue prefetch: chunks 0,1 (each thread copies its 256 B)
    {
        const char* src0 = (const char*)g_pk + tid * 256;
        #pragma unroll
        for (int i = 0; i < 16; ++i)
            cp_async16(smem_b + SPK0 + tid * 256 + i * 16, src0 + i * 16);
        cp_commit();
        const char* src1 = (const char*)g_pk + 32768 + tid * 256;
        #pragma unroll
        for (int i = 0; i < 16; ++i)
            cp_async16(smem_b + SPK1 + tid * 256 + i * 16, src1 + i * 16);
        cp_commit();
    }

    // ---- load x, bit-exact xxr tree, duplicated f32x2 x regs
    unsigned long long xd[DNUM];
    float xxr;
    {
        float xf[DNUM];
        #pragma unroll
        for (int c = 0; c < DNUM; ++c) xf[c] = xp[(size_t)c * 1024];

        float p[32];
        #pragma unroll
        for (int l = 0; l < 32; ++l)
            p[l] = __fadd_rn(__fmul_rn(xf[l], xf[l]), __fmul_rn(xf[l + 32], xf[l + 32]));
        #pragma unroll
        for (int off = 16; off > 0; off >>= 1)
            #pragma unroll
            for (int l = 0; l < 16; ++l)
                if (l < off) p[l] = __fadd_rn(p[l], p[l + off]);
        xxr = p[0];

        #pragma unroll
        for (int d = 0; d < DNUM; ++d) xd[d] = dup2(xf[d]);
    }
    const unsigned long long xxd  = dup2(xxr);
    const unsigned long long neg2 = dup2(-2.0f);

    float best = INFINITY;
    int   bidx = 0;

    for (int c = 0; c < NCHUNK; ++c) {
        const int bufo = (c & 1) ? SPK1 : SPK0;
        cp_wait1();            // chunk c's group complete (≤1 group pending)
        __syncthreads();

        const unsigned long long* spk = (const unsigned long long*)(smem + bufo);
        for (int pp = 0; pp < NPAIR; ++pp) {
            const ulonglong2* cp2 = (const ulonglong2*)(spk + pp * DNUM);
            unsigned long long a0 = 0ull, a1 = 0ull, a2 = 0ull, a3 = 0ull;
            #pragma unroll
            for (int c4 = 0; c4 < 16; ++c4) {
                ulonglong2 v01 = cp2[2 * c4];
                ulonglong2 v23 = cp2[2 * c4 + 1];
                fma2(a0, xd[4 * c4 + 0], v01.x);
                fma2(a1, xd[4 * c4 + 1], v01.y);
                fma2(a2, xd[4 * c4 + 2], v23.x);
                fma2(a3, xd[4 * c4 + 3], v23.y);
            }
            const int pj = c * NPAIR + pp;
            // packed reference assembly (per-lane == proven scalar sequence)
            unsigned long long t2  = add2(add2(a0, a1), add2(a2, a3));
            unsigned long long u2  = add2(xxd, ccp[pj]);
            unsigned long long dk2 = add2(u2, mul2(neg2, t2));
            float dkl, dkh;
            unpk(dkl, dkh, dk2);
            const int j0 = 2 * pj;
            if (dkl < best) { best = dkl; bidx = j0; }      // strict <, ascending
            if (dkh < best) { best = dkh; bidx = j0 + 1; }
        }

        __syncthreads();       // all warps done reading buf before overwrite
        if (c + 2 < NCHUNK) {
            const char* src = (const char*)g_pk + (size_t)(c + 2) * 32768 + tid * 256;
            #pragma unroll
            for (int i = 0; i < 16; ++i)
                cp_async16(smem_b + bufo + tid * 256 + i * 16, src + i * 16);
            cp_commit();
        } else {
            cp_commit();       // keep group accounting uniform
        }
    }

    atomicAdd(&g_hist[bidx], 1);

    // quantized output (= chosen codeword) + MSE; x lanes from xd
    const float* cw = cb + (size_t)bidx * DNUM;
    float*       op = out + (size_t)b * (DNUM * 1024) + hw;
    float mse = 0.f;
    #pragma unroll
    for (int cdim = 0; cdim < DNUM; ++cdim) {
        float cv = cw[cdim];
        op[(size_t)cdim * 1024] = cv;
        float xl, xh;
        unpk(xl, xh, xd[cdim]);
        float dd = cv - xl;
        mse = fmaf(dd, dd, mse);
    }

    __syncthreads();
    sred[tid] = mse;
    __syncthreads();
    for (int s = TB / 2; s > 0; s >>= 1) {
        if (tid < s) sred[tid] += sred[tid + s];
        __syncthreads();
    }
    if (tid == 0) g_msep[blockIdx.x] = sred[0];
}

// ============================================================
// Kernel 2: perplexity, entropic-OT dual ascent, loss.
// __expf only inside the gradient loop (phi enters loss linearly).
// ============================================================
__device__ __forceinline__ float bred(float v, float* red, int t) {
    __syncthreads();
    red[t] = v;
    __syncthreads();
    for (int s = 512; s > 0; s >>= 1) {
        if (t < s) red[t] += red[t + s];
        __syncthreads();
    }
    float r = red[0];
    __syncthreads();
    return r;
}

__global__ __launch_bounds__(1024) void finalize_kernel(float* __restrict__ out) {
    __shared__ float s_src[KNUM], s_tgt[KNUM], s_phi[KNUM], s_lse[KNUM];
    __shared__ float red[1024];
    const int t = threadIdx.x;

    const int hraw = g_hist[t];
    g_hist[t] = 0;
    const float hist = (float)hraw * (1.0f / 32768.0f);

    float ent  = hist * logf(hist + 1e-10f);
    float esum = bred(ent, red, t);
    float perp = expf(-esum);

    float sr  = fmaxf(hist, 1e-12f);
    float ss1 = bred(sr, red, t);
    sr = sr / ss1;
    sr = fmaxf(sr, 1e-12f);
    float ss2 = bred(sr, red, t);
    sr = sr / ss2;
    s_src[t] = sr;

    float z  = ((float)t - 511.5f) / (1024.0f / 6.0f);
    float tg = expf(-0.5f * z * z);
    float ts1 = bred(tg, red, t);
    tg = tg / fmaxf(ts1, 1e-12f);
    tg = fmaxf(tg, 1e-12f);
    float ts2 = bred(tg, red, t);
    tg = tg / ts2;
    s_tgt[t] = tg;
    const float ltg_t = logf(fmaxf(tg, 1e-12f));
    s_phi[t] = 0.f;
    __syncthreads();

    const int lo = (t - HWB < 0) ? 0 : t - HWB;
    const int hi = (t + HWB > KNUM - 1) ? KNUM - 1 : t + HWB;

    float phi_t = 0.f;
    for (int step = 0; step < DUAL_STEPS; ++step) {
        s_lse[t] = __fadd_rn(ltg_t, __fmul_rn(phi_t, 20.0f));
        __syncthreads();
        float cs = 0.f;
        for (int i = lo; i <= hi; ++i) {
            float c = fabsf((float)(i - t));
            float a = __fadd_rn(ltg_t, __fmul_rn(__fadd_rn(-c, phi_t), 20.0f));
            cs = fmaf(s_src[i], __expf(a - s_lse[i]), cs);
        }
        __syncthreads();
        phi_t = phi_t + 0.5f * (s_tgt[t] - cs);
        s_phi[t] = phi_t;
        __syncthreads();
    }

    float lse_t = __fadd_rn(ltg_t, __fmul_rn(phi_t, 20.0f));
    float obj = sr * (-0.05f * lse_t) + s_tgt[t] * phi_t;
    float ot  = bred(obj, red, t);

    float mp   = (t < NBLK) ? g_msep[t] : 0.f;
    float msum = bred(mp, red, t);
    float mse  = msum * (1.0f / 2097152.0f);

    if (t == 0) {
        float loss = mse + 0.25f * mse + 1.0f * ot;
        out[2097152] = loss;
        out[2097153] = perp;
    }
}

// ============================================================
extern "C" void kernel_launch(void* const* d_in, const int* in_sizes, int n_in,
                              void* d_out, int out_size) {
    const float* x  = (const float*)d_in[0];
    const float* cb = (const float*)d_in[1];
    float* out = (float*)d_out;
    (void)in_sizes; (void)n_in; (void)out_size;

    cudaFuncSetAttribute(assign_kernel,
                         cudaFuncAttributeMaxDynamicSharedMemorySize, SM_TOTAL);

    prep_cc<<<8, 128>>>(cb);
    prep_pack<<<4, 128>>>(cb);
    assign_kernel<<<NBLK, TB, SM_TOTAL>>>(x, cb, out);
    finalize_kernel<<<1, 1024>>>(out);
}

// round 12
// speedup vs baseline: 1.1181x; 1.1178x over previous
#include <cuda_runtime.h>
#include <math.h>
#include <stdint.h>

#define KNUM 1024
#define DNUM 64
#define NNUM 32768
#define TB   128            // threads per block = tokens per block
#define NBLK (NNUM / TB)    // 256
#define CH   128            // codes per smem chunk (64 pairs, 32 KB)
#define NPAIR (CH / 2)      // 64 pairs per chunk
#define HWB  6
#define DUAL_STEPS 10

// ---- device scratch ----
__device__ float g_cc[KNUM];
__device__ unsigned long long g_pk[KNUM / 2 * DNUM];  // packed codebook {c[2p][d], c[2p+1][d]}
__device__ int   g_hist[KNUM];      // zero at load; finalize re-zeroes each replay
__device__ float g_msep[NBLK];

// packed f32x2 helpers (each lane is an independent IEEE-rn op == scalar fmaf)
__device__ __forceinline__ void fma2(unsigned long long& acc,
                                     unsigned long long a, unsigned long long b) {
    asm("fma.rn.f32x2 %0, %1, %2, %0;" : "+l"(acc) : "l"(a), "l"(b));
}
__device__ __forceinline__ unsigned long long dup2(float v) {
    unsigned long long r;
    asm("mov.b64 %0, {%1, %1};" : "=l"(r) : "f"(v));
    return r;
}
__device__ __forceinline__ void unpk(float& lo, float& hi, unsigned long long v) {
    asm("mov.b64 {%0, %1}, %2;" : "=f"(lo), "=f"(hi) : "l"(v));
}

// ============================================================
// Kernel 0: cc (bit-exact sequential fmaf chain per code) +
// pairwise packed codebook, one kernel. thread = code pair.
// ============================================================
__global__ __launch_bounds__(128) void prep_kernel(const float* __restrict__ cb) {
    int p = blockIdx.x * 128 + threadIdx.x;   // pair id, grid 4 => 512 pairs
    const float* r0 = cb + (size_t)(2 * p) * DNUM;
    const float* r1 = r0 + DNUM;
    float s0 = 0.f, s1 = 0.f;
    unsigned long long* dst = g_pk + (size_t)p * DNUM;
    #pragma unroll
    for (int d = 0; d < DNUM; ++d) {
        float a = r0[d], b = r1[d];
        s0 = fmaf(a, a, s0);              // bit-exact sequential chain, code 2p
        s1 = fmaf(b, b, s1);              // bit-exact sequential chain, code 2p+1
        dst[d] = (unsigned long long)__float_as_uint(a) |
                 ((unsigned long long)__float_as_uint(b) << 32);
    }
    g_cc[2 * p]     = s0;
    g_cc[2 * p + 1] = s1;
}

// ============================================================
// Kernel 1 (R9 exact): per-token argmin, reference f32 numerics:
//   d_k = fl( fl(xxr + cc_k) - 2*t_k )
//   t_k = 4-chain fmaf dot ((a0+a1)+(a2+a3)) — each f32x2 lane
//         performs the identical rn-rounded op sequence.
// ============================================================
__global__ __launch_bounds__(TB, 2) void assign_kernel(const float* __restrict__ x,
                                                       const float* __restrict__ cb,
                                                       float* __restrict__ out) {
    __shared__ unsigned long long spk[NPAIR * DNUM];   // 32 KB packed chunk
    __shared__ float sccs[KNUM];                       // 4 KB
    __shared__ float sred[TB];

    const int tid = threadIdx.x;
    const int n   = blockIdx.x * TB + tid;
    const int b   = n >> 10;
    const int hw  = n & 1023;
    const float* xp = x + (size_t)b * (DNUM * 1024) + hw;

    #pragma unroll
    for (int i = tid; i < KNUM; i += TB) sccs[i] = g_cc[i];

    // ---- load x, bit-exact xxr tree, build duplicated f32x2 x regs
    float xf[DNUM];
    #pragma unroll
    for (int c = 0; c < DNUM; ++c) xf[c] = xp[(size_t)c * 1024];

    float p[32];
    #pragma unroll
    for (int l = 0; l < 32; ++l)
        p[l] = __fadd_rn(__fmul_rn(xf[l], xf[l]), __fmul_rn(xf[l + 32], xf[l + 32]));
    #pragma unroll
    for (int off = 16; off > 0; off >>= 1)
        #pragma unroll
        for (int l = 0; l < 16; ++l)
            if (l < off) p[l] = __fadd_rn(p[l], p[l + off]);
    const float xxr = p[0];

    unsigned long long xd[DNUM];
    #pragma unroll
    for (int d = 0; d < DNUM; ++d) xd[d] = dup2(xf[d]);

    float best = INFINITY;
    int   bidx = 0;

    for (int k0 = 0; k0 < KNUM; k0 += CH) {
        __syncthreads();
        { // cooperative load of packed chunk (contiguous 32 KB)
            const uint4* src = (const uint4*)(g_pk + (size_t)(k0 / 2) * DNUM);
            uint4*       dst = (uint4*)spk;
            #pragma unroll
            for (int i = 0; i < (NPAIR * DNUM / 2) / TB; ++i)   // 2048/128 = 16
                dst[tid + i * TB] = src[tid + i * TB];
        }
        __syncthreads();

        for (int pp = 0; pp < NPAIR; ++pp) {
            const ulonglong2* cp = (const ulonglong2*)(spk + pp * DNUM);
            unsigned long long a0 = 0ull, a1 = 0ull, a2 = 0ull, a3 = 0ull;
            #pragma unroll
            for (int c4 = 0; c4 < 16; ++c4) {
                ulonglong2 v01 = cp[2 * c4];        // dims 4c4+0, 4c4+1
                ulonglong2 v23 = cp[2 * c4 + 1];    // dims 4c4+2, 4c4+3
                fma2(a0, xd[4 * c4 + 0], v01.x);
                fma2(a1, xd[4 * c4 + 1], v01.y);
                fma2(a2, xd[4 * c4 + 2], v23.x);
                fma2(a3, xd[4 * c4 + 3], v23.y);
            }
            float a0l, a0h, a1l, a1h, a2l, a2h, a3l, a3h;
            unpk(a0l, a0h, a0); unpk(a1l, a1h, a1);
            unpk(a2l, a2h, a2); unpk(a3l, a3h, a3);

            const int j0 = k0 + 2 * pp;
            // code j0 (exact reference assembly)
            {
                float t  = __fadd_rn(__fadd_rn(a0l, a1l), __fadd_rn(a2l, a3l));
                float u  = __fadd_rn(xxr, sccs[j0]);
                float dk = __fadd_rn(u, __fmul_rn(-2.f, t));
                if (dk < best) { best = dk; bidx = j0; }
            }
            // code j0+1 (after j0 => ascending first-index preserved)
            {
                float t  = __fadd_rn(__fadd_rn(a0h, a1h), __fadd_rn(a2h, a3h));
                float u  = __fadd_rn(xxr, sccs[j0 + 1]);
                float dk = __fadd_rn(u, __fmul_rn(-2.f, t));
                if (dk < best) { best = dk; bidx = j0 + 1; }
            }
        }
    }

    atomicAdd(&g_hist[bidx], 1);

    // quantized output (= chosen codeword) in [B,C,H,W] layout + MSE
    const float* cw = cb + (size_t)bidx * DNUM;
    float*       op = out + (size_t)b * (DNUM * 1024) + hw;
    float mse = 0.f;
    #pragma unroll
    for (int c = 0; c < DNUM; ++c) {
        float cv = cw[c];
        op[(size_t)c * 1024] = cv;
        float dd = cv - xf[c];
        mse = fmaf(dd, dd, mse);
    }

    __syncthreads();
    sred[tid] = mse;
    __syncthreads();
    for (int s = TB / 2; s > 0; s >>= 1) {
        if (tid < s) sred[tid] += sred[tid + s];
        __syncthreads();
    }
    if (tid == 0) g_msep[blockIdx.x] = sred[0];
}

// ============================================================
// Kernel 2: perplexity, entropic-OT dual ascent, loss.
// Shuffle-tree block reduction: 3 barriers instead of 11.
// __expf only inside the gradient loop (phi enters loss linearly).
// ============================================================
__device__ __forceinline__ float bred(float v, float* red32, int t) {
    #pragma unroll
    for (int off = 16; off > 0; off >>= 1)
        v += __shfl_down_sync(0xFFFFFFFFu, v, off);
    const int w = t >> 5, lane = t & 31;
    if (lane == 0) red32[w] = v;
    __syncthreads();
    if (w == 0) {
        float s = red32[lane];
        #pragma unroll
        for (int off = 16; off > 0; off >>= 1)
            s += __shfl_down_sync(0xFFFFFFFFu, s, off);
        if (lane == 0) red32[0] = s;
    }
    __syncthreads();
    float r = red32[0];
    __syncthreads();
    return r;
}

__global__ __launch_bounds__(1024) void finalize_kernel(float* __restrict__ out) {
    __shared__ float s_src[KNUM], s_tgt[KNUM], s_phi[KNUM], s_lse[KNUM];
    __shared__ float red32[32];
    const int t = threadIdx.x;

    const int hraw = g_hist[t];
    g_hist[t] = 0;
    const float hist = (float)hraw * (1.0f / 32768.0f);

    float ent  = hist * logf(hist + 1e-10f);
    float esum = bred(ent, red32, t);
    float perp = expf(-esum);

    float sr  = fmaxf(hist, 1e-12f);
    float ss1 = bred(sr, red32, t);
    sr = sr / ss1;
    sr = fmaxf(sr, 1e-12f);
    float ss2 = bred(sr, red32, t);
    sr = sr / ss2;
    s_src[t] = sr;

    float z  = ((float)t - 511.5f) / (1024.0f / 6.0f);
    float tg = expf(-0.5f * z * z);
    float ts1 = bred(tg, red32, t);
    tg = tg / fmaxf(ts1, 1e-12f);
    tg = fmaxf(tg, 1e-12f);
    float ts2 = bred(tg, red32, t);
    tg = tg / ts2;
    s_tgt[t] = tg;
    const float ltg_t = logf(fmaxf(tg, 1e-12f));
    s_phi[t] = 0.f;
    __syncthreads();

    const int lo = (t - HWB < 0) ? 0 : t - HWB;
    const int hi = (t + HWB > KNUM - 1) ? KNUM - 1 : t + HWB;

    float phi_t = 0.f;
    for (int step = 0; step < DUAL_STEPS; ++step) {
        // analytic lse (off-max softmax terms < half-ulp(1.0) in f32)
        s_lse[t] = __fadd_rn(ltg_t, __fmul_rn(phi_t, 20.0f));
        __syncthreads();
        float cs = 0.f;
        for (int i = lo; i <= hi; ++i) {
            float c = fabsf((float)(i - t));
            float a = __fadd_rn(ltg_t, __fmul_rn(__fadd_rn(-c, phi_t), 20.0f));
            cs = fmaf(s_src[i], __expf(a - s_lse[i]), cs);
        }
        __syncthreads();
        phi_t = phi_t + 0.5f * (s_tgt[t] - cs);
        s_phi[t] = phi_t;
        __syncthreads();
    }

    float lse_t = __fadd_rn(ltg_t, __fmul_rn(phi_t, 20.0f));
    float obj = sr * (-0.05f * lse_t) + s_tgt[t] * phi_t;
    float ot  = bred(obj, red32, t);

    float mp   = (t < NBLK) ? g_msep[t] : 0.f;
    float msum = bred(mp, red32, t);
    float mse  = msum * (1.0f / 2097152.0f);

    if (t == 0) {
        float loss = mse + 0.25f * mse + 1.0f * ot;
        out[2097152] = loss;
        out[2097153] = perp;
    }
}

// ============================================================
extern "C" void kernel_launch(void* const* d_in, const int* in_sizes, int n_in,
                              void* d_out, int out_size) {
    const float* x  = (const float*)d_in[0];
    const float* cb = (const float*)d_in[1];
    float* out = (float*)d_out;
    (void)in_sizes; (void)n_in; (void)out_size;

    prep_kernel<<<4, 128>>>(cb);
    assign_kernel<<<NBLK, TB>>>(x, cb, out);
    finalize_kernel<<<1, 1024>>>(out);
}

// round 13
// speedup vs baseline: 1.1934x; 1.0673x over previous
#include <cuda_runtime.h>
#include <math.h>
#include <stdint.h>

#define KNUM 1024
#define DNUM 64
#define NNUM 32768
#define TB   128            // threads per block = tokens per block
#define NBLK (NNUM / TB)    // 256
#define CH   128            // codes per smem chunk (64 pairs, 32 KB)
#define NPAIR (CH / 2)      // 64 pairs per chunk
#define HWB  6
#define DUAL_STEPS 10

// ---- device scratch ----
__device__ float g_cc[KNUM];
__device__ unsigned long long g_pk[KNUM / 2 * DNUM];  // packed codebook {c[2p][d], c[2p+1][d]}
__device__ int   g_hist[KNUM];      // zero at load; finalize re-zeroes each replay
__device__ float g_msep[NBLK];

// packed f32x2 helpers (each lane is an independent IEEE-rn op == scalar fmaf)
__device__ __forceinline__ void fma2(unsigned long long& acc,
                                     unsigned long long a, unsigned long long b) {
    asm("fma.rn.f32x2 %0, %1, %2, %0;" : "+l"(acc) : "l"(a), "l"(b));
}
__device__ __forceinline__ unsigned long long dup2(float v) {
    unsigned long long r;
    asm("mov.b64 %0, {%1, %1};" : "=l"(r) : "f"(v));
    return r;
}
__device__ __forceinline__ void unpk(float& lo, float& hi, unsigned long long v) {
    asm("mov.b64 {%0, %1}, %2;" : "=f"(lo), "=f"(hi) : "l"(v));
}

// ============================================================
// Kernel 0: coalesced prep. Block = 128 codes (64 pairs).
//  1) coalesced uint4 load of the 32 KB codebook chunk to smem
//  2) per-code cc via the bit-exact sequential fmaf chain (from smem)
//  3) coalesced u64 writes of the pairwise-packed table
// ============================================================
__global__ __launch_bounds__(128) void prep_kernel(const float* __restrict__ cb) {
    __shared__ float scb[CH * DNUM];            // 32 KB
    const int tid = threadIdx.x;
    const int k0  = blockIdx.x * CH;            // first code of this chunk

    { // coalesced load: 2048 uint4
        const uint4* src = (const uint4*)(cb + (size_t)k0 * DNUM);
        uint4*       dst = (uint4*)scb;
        #pragma unroll
        for (int i = 0; i < (CH * DNUM / 4) / 128; ++i)   // 16 iters
            dst[tid + i * 128] = src[tid + i * 128];
    }
    __syncthreads();

    { // cc: thread = code, bit-exact sequential fmaf chain
        const float* r = scb + tid * DNUM;
        float s = 0.f;
        #pragma unroll
        for (int d = 0; d < DNUM; ++d) s = fmaf(r[d], r[d], s);
        g_cc[k0 + tid] = s;
    }

    { // pack: output element i -> pair p=i/64, dim d=i%64 (coalesced 8B writes)
        unsigned long long* dst = g_pk + (size_t)(k0 / 2) * DNUM;
        #pragma unroll
        for (int i = tid; i < NPAIR * DNUM; i += 128) {
            int p = i >> 6, d = i & 63;
            dst[i] = (unsigned long long)__float_as_uint(scb[(2 * p) * DNUM + d]) |
                     ((unsigned long long)__float_as_uint(scb[(2 * p + 1) * DNUM + d]) << 32);
        }
    }
}

// ============================================================
// Kernel 1 (R9 exact): per-token argmin, reference f32 numerics:
//   d_k = fl( fl(xxr + cc_k) - 2*t_k )
//   t_k = 4-chain fmaf dot ((a0+a1)+(a2+a3)) — each f32x2 lane
//         performs the identical rn-rounded op sequence.
// ============================================================
__global__ __launch_bounds__(TB, 2) void assign_kernel(const float* __restrict__ x,
                                                       const float* __restrict__ cb,
                                                       float* __restrict__ out) {
    __shared__ unsigned long long spk[NPAIR * DNUM];   // 32 KB packed chunk
    __shared__ float sccs[KNUM];                       // 4 KB
    __shared__ float sred[TB];

    const int tid = threadIdx.x;
    const int n   = blockIdx.x * TB + tid;
    const int b   = n >> 10;
    const int hw  = n & 1023;
    const float* xp = x + (size_t)b * (DNUM * 1024) + hw;

    #pragma unroll
    for (int i = tid; i < KNUM; i += TB) sccs[i] = g_cc[i];

    // ---- load x, bit-exact xxr tree, build duplicated f32x2 x regs
    float xf[DNUM];
    #pragma unroll
    for (int c = 0; c < DNUM; ++c) xf[c] = xp[(size_t)c * 1024];

    float p[32];
    #pragma unroll
    for (int l = 0; l < 32; ++l)
        p[l] = __fadd_rn(__fmul_rn(xf[l], xf[l]), __fmul_rn(xf[l + 32], xf[l + 32]));
    #pragma unroll
    for (int off = 16; off > 0; off >>= 1)
        #pragma unroll
        for (int l = 0; l < 16; ++l)
            if (l < off) p[l] = __fadd_rn(p[l], p[l + off]);
    const float xxr = p[0];

    unsigned long long xd[DNUM];
    #pragma unroll
    for (int d = 0; d < DNUM; ++d) xd[d] = dup2(xf[d]);

    float best = INFINITY;
    int   bidx = 0;

    for (int k0 = 0; k0 < KNUM; k0 += CH) {
        __syncthreads();
        { // cooperative load of packed chunk (contiguous 32 KB)
            const uint4* src = (const uint4*)(g_pk + (size_t)(k0 / 2) * DNUM);
            uint4*       dst = (uint4*)spk;
            #pragma unroll
            for (int i = 0; i < (NPAIR * DNUM / 2) / TB; ++i)   // 16 iters
                dst[tid + i * TB] = src[tid + i * TB];
        }
        __syncthreads();

        for (int pp = 0; pp < NPAIR; ++pp) {
            const ulonglong2* cp = (const ulonglong2*)(spk + pp * DNUM);
            unsigned long long a0 = 0ull, a1 = 0ull, a2 = 0ull, a3 = 0ull;
            #pragma unroll
            for (int c4 = 0; c4 < 16; ++c4) {
                ulonglong2 v01 = cp[2 * c4];        // dims 4c4+0, 4c4+1
                ulonglong2 v23 = cp[2 * c4 + 1];    // dims 4c4+2, 4c4+3
                fma2(a0, xd[4 * c4 + 0], v01.x);
                fma2(a1, xd[4 * c4 + 1], v01.y);
                fma2(a2, xd[4 * c4 + 2], v23.x);
                fma2(a3, xd[4 * c4 + 3], v23.y);
            }
            float a0l, a0h, a1l, a1h, a2l, a2h, a3l, a3h;
            unpk(a0l, a0h, a0); unpk(a1l, a1h, a1);
            unpk(a2l, a2h, a2); unpk(a3l, a3h, a3);

            const int j0 = k0 + 2 * pp;
            // code j0 (exact reference assembly)
            {
                float t  = __fadd_rn(__fadd_rn(a0l, a1l), __fadd_rn(a2l, a3l));
                float u  = __fadd_rn(xxr, sccs[j0]);
                float dk = __fadd_rn(u, __fmul_rn(-2.f, t));
                if (dk < best) { best = dk; bidx = j0; }
            }
            // code j0+1 (after j0 => ascending first-index preserved)
            {
                float t  = __fadd_rn(__fadd_rn(a0h, a1h), __fadd_rn(a2h, a3h));
                float u  = __fadd_rn(xxr, sccs[j0 + 1]);
                float dk = __fadd_rn(u, __fmul_rn(-2.f, t));
                if (dk < best) { best = dk; bidx = j0 + 1; }
            }
        }
    }

    atomicAdd(&g_hist[bidx], 1);

    // quantized output (= chosen codeword) in [B,C,H,W] layout + MSE
    const float* cw = cb + (size_t)bidx * DNUM;
    float*       op = out + (size_t)b * (DNUM * 1024) + hw;
    float mse = 0.f;
    #pragma unroll
    for (int c = 0; c < DNUM; ++c) {
        float cv = cw[c];
        op[(size_t)c * 1024] = cv;
        float dd = cv - xf[c];
        mse = fmaf(dd, dd, mse);
    }

    __syncthreads();
    sred[tid] = mse;
    __syncthreads();
    for (int s = TB / 2; s > 0; s >>= 1) {
        if (tid < s) sred[tid] += sred[tid + s];
        __syncthreads();
    }
    if (tid == 0) g_msep[blockIdx.x] = sred[0];
}

// ============================================================
// Kernel 2: perplexity, entropic-OT dual ascent, loss.
// Shuffle-tree block reduction (3 barriers), analytic lse,
// __expf in the gradient loop only.
// ============================================================
__device__ __forceinline__ float bred(float v, float* red32, int t) {
    #pragma unroll
    for (int off = 16; off > 0; off >>= 1)
        v += __shfl_down_sync(0xFFFFFFFFu, v, off);
    const int w = t >> 5, lane = t & 31;
    if (lane == 0) red32[w] = v;
    __syncthreads();
    if (w == 0) {
        float s = red32[lane];
        #pragma unroll
        for (int off = 16; off > 0; off >>= 1)
            s += __shfl_down_sync(0xFFFFFFFFu, s, off);
        if (lane == 0) red32[0] = s;
    }
    __syncthreads();
    float r = red32[0];
    __syncthreads();
    return r;
}

__global__ __launch_bounds__(1024) void finalize_kernel(float* __restrict__ out) {
    __shared__ float s_src[KNUM], s_tgt[KNUM], s_phi[KNUM], s_lse[KNUM];
    __shared__ float red32[32];
    const int t = threadIdx.x;

    const int hraw = g_hist[t];
    g_hist[t] = 0;
    const float hist = (float)hraw * (1.0f / 32768.0f);

    float ent  = hist * logf(hist + 1e-10f);
    float esum = bred(ent, red32, t);
    float perp = expf(-esum);

    float sr  = fmaxf(hist, 1e-12f);
    float ss1 = bred(sr, red32, t);
    sr = sr / ss1;
    sr = fmaxf(sr, 1e-12f);
    float ss2 = bred(sr, red32, t);
    sr = sr / ss2;
    s_src[t] = sr;

    float z  = ((float)t - 511.5f) / (1024.0f / 6.0f);
    float tg = expf(-0.5f * z * z);
    float ts1 = bred(tg, red32, t);
    tg = tg / fmaxf(ts1, 1e-12f);
    tg = fmaxf(tg, 1e-12f);
    float ts2 = bred(tg, red32, t);
    tg = tg / ts2;
    s_tgt[t] = tg;
    const float ltg_t = logf(fmaxf(tg, 1e-12f));
    s_phi[t] = 0.f;
    __syncthreads();

    const int lo = (t - HWB < 0) ? 0 : t - HWB;
    const int hi = (t + HWB > KNUM - 1) ? KNUM - 1 : t + HWB;

    float phi_t = 0.f;
    for (int step = 0; step < DUAL_STEPS; ++step) {
        // analytic lse (off-max softmax terms < half-ulp(1.0) in f32)
        s_lse[t] = __fadd_rn(ltg_t, __fmul_rn(phi_t, 20.0f));
        __syncthreads();
        float cs = 0.f;
        for (int i = lo; i <= hi; ++i) {
            float c = fabsf((float)(i - t));
            float a = __fadd_rn(ltg_t, __fmul_rn(__fadd_rn(-c, phi_t), 20.0f));
            cs = fmaf(s_src[i], __expf(a - s_lse[i]), cs);
        }
        __syncthreads();
        phi_t = phi_t + 0.5f * (s_tgt[t] - cs);
        s_phi[t] = phi_t;
        __syncthreads();
    }

    float lse_t = __fadd_rn(ltg_t, __fmul_rn(phi_t, 20.0f));
    float obj = sr * (-0.05f * lse_t) + s_tgt[t] * phi_t;
    float ot  = bred(obj, red32, t);

    float mp   = (t < NBLK) ? g_msep[t] : 0.f;
    float msum = bred(mp, red32, t);
    float mse  = msum * (1.0f / 2097152.0f);

    if (t == 0) {
        float loss = mse + 0.25f * mse + 1.0f * ot;
        out[2097152] = loss;
        out[2097153] = perp;
    }
}

// ============================================================
extern "C" void kernel_launch(void* const* d_in, const int* in_sizes, int n_in,
                              void* d_out, int out_size) {
    const float* x  = (const float*)d_in[0];
    const float* cb = (const float*)d_in[1];
    float* out = (float*)d_out;
    (void)in_sizes; (void)n_in; (void)out_size;

    prep_kernel<<<KNUM / CH, 128>>>(cb);     // 8 blocks
    assign_kernel<<<NBLK, TB>>>(x, cb, out);
    finalize_kernel<<<1, 1024>>>(out);
}